// round 9
// baseline (speedup 1.0000x reference)
#include <cuda_runtime.h>

// Problem constants (fixed by the dataset)
#define NB 1024
#define NM 8192
#define NN 32
#define NS 128

// Tiling
#define BT 128                         // b rows per block
#define MC 16                          // m per chunk
#define MSPLIT 32                      // blocks along m
#define NCHUNK ((NM / MC) / MSPLIT)    // 16 chunks per block
#define NTHREADS 256

// Scratch (no allocation allowed -> device globals)
__device__ float  g_kv[2 * NN * NM];          // [64][M]: rows 0..31 = z_j^T, 32..63 = b_unit^T
__device__ float4 g_par0[NM];                 // {w_perp, w_perp*|z_j|^2, -2*w_perp, w_diff}
__device__ float2 g_par1[NM];                 // {c = z_j.b_unit, alpha}
__device__ float  g_zn[NB];                   // |z_b|^2
__device__ float  g_part[MSPLIT * NB * NS];   // 16 MB partial outputs

__global__ void pre_z_kernel(const float* __restrict__ z) {
    int b = blockIdx.x * blockDim.x + threadIdx.x;
    if (b >= NB) return;
    const float4* z4 = reinterpret_cast<const float4*>(z + b * NN);
    float s = 0.f;
    #pragma unroll
    for (int i = 0; i < NN / 4; i++) {
        float4 v = z4[i];
        s = fmaf(v.x, v.x, s); s = fmaf(v.y, v.y, s);
        s = fmaf(v.z, v.z, s); s = fmaf(v.w, v.w, s);
    }
    g_zn[b] = s;
}

__global__ void pre_m_kernel(const float* __restrict__ zj, const float* __restrict__ vd,
                             const float* __restrict__ alpha, const float* __restrict__ sp,
                             const float* __restrict__ spr) {
    int m = blockIdx.x * blockDim.x + threadIdx.x;
    if (m >= NM) return;
    const float4* z4 = reinterpret_cast<const float4*>(zj + m * NN);
    const float4* d4 = reinterpret_cast<const float4*>(vd + m * NN);
    float d2 = 0.f, zz = 0.f, cr = 0.f;
    #pragma unroll
    for (int i = 0; i < NN / 4; i++) {
        float4 d = d4[i], zv = z4[i];
        d2 = fmaf(d.x, d.x, d2);  d2 = fmaf(d.y, d.y, d2);
        d2 = fmaf(d.z, d.z, d2);  d2 = fmaf(d.w, d.w, d2);
        zz = fmaf(zv.x, zv.x, zz); zz = fmaf(zv.y, zv.y, zz);
        zz = fmaf(zv.z, zv.z, zz); zz = fmaf(zv.w, zv.w, zz);
        cr = fmaf(zv.x, d.x, cr);  cr = fmaf(zv.y, d.y, cr);
        cr = fmaf(zv.z, d.z, cr);  cr = fmaf(zv.w, d.w, cr);
    }
    float dn  = sqrtf(d2);
    float inv = (dn > 1e-6f) ? (1.0f / dn) : 0.0f;   // EPS = 1e-6, strict >
    // Transposed writes: warp lanes are consecutive m -> coalesced per row k
    #pragma unroll
    for (int i = 0; i < NN / 4; i++) {
        float4 d = d4[i], zv = z4[i];
        g_kv[(4 * i + 0) * NM + m] = zv.x;
        g_kv[(4 * i + 1) * NM + m] = zv.y;
        g_kv[(4 * i + 2) * NM + m] = zv.z;
        g_kv[(4 * i + 3) * NM + m] = zv.w;
        g_kv[(NN + 4 * i + 0) * NM + m] = d.x * inv;
        g_kv[(NN + 4 * i + 1) * NM + m] = d.y * inv;
        g_kv[(NN + 4 * i + 2) * NM + m] = d.z * inv;
        g_kv[(NN + 4 * i + 3) * NM + m] = d.w * inv;
    }
    const float tiny = 1.1920929e-7f;   // float32 machine eps (jnp.finfo.eps)
    float a  = fmaxf(sp[m],  tiny);
    float bb = fmaxf(spr[m], tiny);
    float w_par  = 1.f / (a * a);
    float w_perp = 1.f / (bb * bb);
    g_par0[m] = make_float4(w_perp, w_perp * zz, -2.f * w_perp, w_par - w_perp);
    g_par1[m] = make_float2(cr * inv, alpha[m]);
}

__global__ void __launch_bounds__(NTHREADS, 2)
fused_kernel(const float* __restrict__ z, const float* __restrict__ that) {
    __shared__ float z_t[NN][BT];        // 16 KB, z transposed: [k][b]
    __shared__ float zn_sh[BT];          // 0.5 KB
    __shared__ float kv_sh[2 * NN][MC];  // 4 KB, [k][m] (rows 0..31 z_j, 32..63 b_unit)
    __shared__ float gain_sh[MC][BT];    // 8 KB
    __shared__ float that_sh[MC][NS];    // 8 KB

    const int tid    = threadIdx.x;
    const int b_base = blockIdx.x * BT;
    const int ms     = blockIdx.y;

    // Load z tile transposed (one-time)
    for (int idx = tid; idx < BT * NN; idx += NTHREADS) {
        int bb = idx >> 5, k = idx & 31;
        z_t[k][bb] = z[(b_base + bb) * NN + k];
    }
    if (tid < BT) zn_sh[tid] = g_zn[b_base + tid];

    // Phase-1 mapping: 4 b x 2 m per thread (warp = 32 b-quads, same m-pair -> kv broadcast)
    const int bq  = tid & 31;
    const int mp  = tid >> 5;
    const int b0  = bq * 4;
    const int m0  = mp * 2;
    // Phase-2 mapping: 8 b x 8 s register tile
    const int sx  = tid & 15;
    const int byy = tid >> 4;
    const int s0  = sx * 8;
    const int pb0 = byy * 8;

    unsigned long long acc[8][4];        // 8 b-rows x 4 f32x2 pairs (8 s)
    #pragma unroll
    for (int i = 0; i < 8; i++)
        #pragma unroll
        for (int j = 0; j < 4; j++) acc[i][j] = 0ull;

    const int chunk0 = ms * NCHUNK;
    for (int ch = 0; ch < NCHUNK; ch++) {
        const int mbase = (chunk0 + ch) * MC;
        __syncthreads();   // previous chunk's readers done before overwriting smem

        // Cooperative load kv chunk: 64 x 16 floats = 256 float4, one per thread
        {
            int k = tid >> 2, mq = tid & 3;
            reinterpret_cast<float4*>(&kv_sh[k][0])[mq] =
                __ldg(reinterpret_cast<const float4*>(g_kv + k * NM + mbase) + mq);
        }
        // Cooperative load T_hat chunk: 16 x 128 floats = 512 float4, two per thread
        #pragma unroll
        for (int t = 0; t < 2; t++) {
            int f  = tid + t * NTHREADS;
            int mm = f >> 5, sq = f & 31;
            reinterpret_cast<float4*>(&that_sh[mm][0])[sq] =
                __ldg(reinterpret_cast<const float4*>(that + (size_t)(mbase + mm) * NS) + sq);
        }
        __syncthreads();

        // ---- Phase 1: gains for this chunk (two dots per pair, f32x2 over m-pair) ----
        {
            unsigned long long u2[4], v2[4];
            #pragma unroll
            for (int i = 0; i < 4; i++) { u2[i] = 0ull; v2[i] = 0ull; }
            #pragma unroll
            for (int k = 0; k < NN; k++) {
                float4 z4 = *reinterpret_cast<const float4*>(&z_t[k][b0]);
                unsigned long long zj2 = *reinterpret_cast<const unsigned long long*>(&kv_sh[k][m0]);
                unsigned long long bv2 = *reinterpret_cast<const unsigned long long*>(&kv_sh[NN + k][m0]);
                const float zf[4] = {z4.x, z4.y, z4.z, z4.w};
                #pragma unroll
                for (int i = 0; i < 4; i++) {
                    unsigned long long zd;
                    asm("mov.b64 %0, {%1, %1};" : "=l"(zd) : "r"(__float_as_uint(zf[i])));
                    asm("fma.rn.f32x2 %0, %1, %2, %0;" : "+l"(u2[i]) : "l"(zd), "l"(zj2));
                    asm("fma.rn.f32x2 %0, %1, %2, %0;" : "+l"(v2[i]) : "l"(zd), "l"(bv2));
                }
            }
            float4 pA = g_par0[mbase + m0];
            float4 pB = g_par0[mbase + m0 + 1];
            float2 cA = g_par1[mbase + m0];
            float2 cB = g_par1[mbase + m0 + 1];
            float4 gOutA, gOutB;
            float* gA = &gOutA.x;
            float* gB = &gOutB.x;
            #pragma unroll
            for (int i = 0; i < 4; i++) {
                float ua, ub, va, vb;
                asm("mov.b64 {%0, %1}, %2;" : "=f"(ua), "=f"(ub) : "l"(u2[i]));
                asm("mov.b64 {%0, %1}, %2;" : "=f"(va), "=f"(vb) : "l"(v2[i]));
                float znb = zn_sh[b0 + i];
                // q = w_perp*|z|^2 + w_perp*|zj|^2 - 2*w_perp*(z.zj) + w_diff*(z.b - c)^2
                float ta = va - cA.x;
                float qa = fmaf(pA.x, znb, pA.y);
                qa = fmaf(pA.z, ua, qa);
                qa = fmaf(pA.w * ta, ta, qa);
                qa = fminf(qa, 25.f);
                gA[i] = cA.y * __expf(-3.14159265358979323846f * qa);
                float tb = vb - cB.x;
                float qb = fmaf(pB.x, znb, pB.y);
                qb = fmaf(pB.z, ub, qb);
                qb = fmaf(pB.w * tb, tb, qb);
                qb = fminf(qb, 25.f);
                gB[i] = cB.y * __expf(-3.14159265358979323846f * qb);
            }
            *reinterpret_cast<float4*>(&gain_sh[m0][b0])     = gOutA;
            *reinterpret_cast<float4*>(&gain_sh[m0 + 1][b0]) = gOutB;
        }
        __syncthreads();

        // ---- Phase 2: acc[8b][8s] += gain[8b][mc] * that[mc][8s]  (f32x2 over s) ----
        #pragma unroll
        for (int mc = 0; mc < MC; mc++) {
            float4 ga = *reinterpret_cast<const float4*>(&gain_sh[mc][pb0]);
            float4 gb = *reinterpret_cast<const float4*>(&gain_sh[mc][pb0 + 4]);
            ulonglong2 tlo = *reinterpret_cast<const ulonglong2*>(&that_sh[mc][s0]);
            ulonglong2 thi = *reinterpret_cast<const ulonglong2*>(&that_sh[mc][s0 + 4]);
            unsigned long long t2[4] = {tlo.x, tlo.y, thi.x, thi.y};
            const float gsc[8] = {ga.x, ga.y, ga.z, ga.w, gb.x, gb.y, gb.z, gb.w};
            #pragma unroll
            for (int i = 0; i < 8; i++) {
                unsigned long long gd;
                asm("mov.b64 %0, {%1, %1};" : "=l"(gd) : "r"(__float_as_uint(gsc[i])));
                #pragma unroll
                for (int j = 0; j < 4; j++)
                    asm("fma.rn.f32x2 %0, %1, %2, %0;" : "+l"(acc[i][j]) : "l"(gd), "l"(t2[j]));
            }
        }
    }

    // Flush accumulators to partial buffer (fully written across grid)
    float* outp = g_part + (size_t)ms * (NB * NS) + (size_t)(b_base + pb0) * NS + s0;
    #pragma unroll
    for (int i = 0; i < 8; i++) {
        float2 f0 = *reinterpret_cast<float2*>(&acc[i][0]);
        float2 f1 = *reinterpret_cast<float2*>(&acc[i][1]);
        float2 f2 = *reinterpret_cast<float2*>(&acc[i][2]);
        float2 f3 = *reinterpret_cast<float2*>(&acc[i][3]);
        *reinterpret_cast<float4*>(outp + (size_t)i * NS)     = make_float4(f0.x, f0.y, f1.x, f1.y);
        *reinterpret_cast<float4*>(outp + (size_t)i * NS + 4) = make_float4(f2.x, f2.y, f3.x, f3.y);
    }
}

__global__ void reduce_kernel(float* __restrict__ out) {
    int idx = blockIdx.x * blockDim.x + threadIdx.x;   // 0 .. B*S/4-1
    const float4* gp = reinterpret_cast<const float4*>(g_part);
    float4 a = make_float4(0.f, 0.f, 0.f, 0.f);
    #pragma unroll
    for (int p = 0; p < MSPLIT; p++) {
        float4 v = gp[(size_t)p * (NB * NS / 4) + idx];
        a.x += v.x; a.y += v.y; a.z += v.z; a.w += v.w;
    }
    reinterpret_cast<float4*>(out)[idx] = a;
}

extern "C" void kernel_launch(void* const* d_in, const int* in_sizes, int n_in,
                              void* d_out, int out_size) {
    const float* z     = (const float*)d_in[0];   // [B, N]
    const float* zj    = (const float*)d_in[1];   // [M, N]
    const float* vd    = (const float*)d_in[2];   // [M, N]
    const float* that  = (const float*)d_in[3];   // [M, S]
    const float* alpha = (const float*)d_in[4];   // [M]
    const float* sp    = (const float*)d_in[5];   // [M]
    const float* spr   = (const float*)d_in[6];   // [M]
    float* out = (float*)d_out;                   // [B, S] fp32

    pre_z_kernel<<<(NB + 255) / 256, 256>>>(z);
    pre_m_kernel<<<(NM + 255) / 256, 256>>>(zj, vd, alpha, sp, spr);
    fused_kernel<<<dim3(NB / BT, MSPLIT), NTHREADS>>>(z, that);
    reduce_kernel<<<(NB * NS / 4 + 255) / 256, 256>>>(out);
}

// round 11
// speedup vs baseline: 1.3967x; 1.3967x over previous
#include <cuda_runtime.h>
#include <cuda_bf16.h>
#include <cstdint>

#define NB 1024
#define NM 8192
#define NN 32
#define NS 128
#define MSPLIT 16
#define NCHUNK 16
#define NGRP 256
#define PI_F 3.14159265358979f

// static smem layout (byte offsets); all row strides are multiples of 16B
#define SM_Z   0        // z   [128][40] bf16  (stride 80B)  = 10240
#define SM_W   10240    // W   [32][72]  bf16  (stride 144B) = 4608
#define SM_B   14848    // B   [64][72]  bf16  (stride 144B) = 9216
#define SM_A2  24064    // A2  [128][72] bf16  (stride 144B) = 18432
#define SM_P0  42496    // 32 x float4
#define SM_P1  43008    // 32 x float2
#define SM_TOT 43264

// device scratch (no allocation allowed)
__device__ __nv_bfloat16 g_zt[8 * 128 * 32];        // per b-tile [128][32] bf16
__device__ float         g_zn[NB];
__device__ __nv_bfloat16 g_WB[NGRP * 32 * 64];      // per grp [32 k][64 n] (n: 0-31 zj, 32-63 bhat)
__device__ __nv_bfloat16 g_TB[NGRP * 64 * 128];     // per grp [64 k][128 s] (k: 0-31 th, 32-63 tl)
__device__ float4        g_par0[NM];                // {w_perp, w_perp*|zj|^2, -2*w_perp, w_diff}
__device__ float2        g_par1[NM];                // {c, alpha}
__device__ float         g_part[(size_t)MSPLIT * NB * NS];   // 8 MB partials

__device__ __forceinline__ uint32_t smem_u32(const void* p) {
    uint32_t a;
    asm("{ .reg .u64 t; cvta.to.shared.u64 t, %1; cvt.u32.u64 %0, t; }" : "=r"(a) : "l"(p));
    return a;
}
__device__ __forceinline__ void ldsm4(uint32_t* r, uint32_t a) {
    asm volatile("ldmatrix.sync.aligned.m8n8.x4.shared.b16 {%0,%1,%2,%3}, [%4];"
        : "=r"(r[0]), "=r"(r[1]), "=r"(r[2]), "=r"(r[3]) : "r"(a));
}
__device__ __forceinline__ void ldsm4t(uint32_t* r, uint32_t a) {
    asm volatile("ldmatrix.sync.aligned.m8n8.x4.trans.shared.b16 {%0,%1,%2,%3}, [%4];"
        : "=r"(r[0]), "=r"(r[1]), "=r"(r[2]), "=r"(r[3]) : "r"(a));
}
__device__ __forceinline__ void mmabf(float* c, const uint32_t* a, uint32_t b0, uint32_t b1) {
    asm volatile("mma.sync.aligned.m16n8k16.row.col.f32.bf16.bf16.f32 "
        "{%0,%1,%2,%3}, {%4,%5,%6,%7}, {%8,%9}, {%0,%1,%2,%3};"
        : "+f"(c[0]), "+f"(c[1]), "+f"(c[2]), "+f"(c[3])
        : "r"(a[0]), "r"(a[1]), "r"(a[2]), "r"(a[3]), "r"(b0), "r"(b1));
}
// ldmatrix x4 per-lane address: mats = (r0,k0),(r8,k0),(r0,k8),(r8,k8)
__device__ __forceinline__ uint32_t lmaddr(uint32_t base, int rowB, int colB, int strideB,
                                           int mat, int lr) {
    return base + (uint32_t)((rowB + lr + 8 * (mat & 1)) * strideB + (colB + 8 * (mat >> 1)) * 2);
}
__device__ __forceinline__ uint32_t pk(__nv_bfloat16 a, __nv_bfloat16 b) {
    __nv_bfloat162 t; t.x = a; t.y = b;
    return *reinterpret_cast<uint32_t*>(&t);
}

// ---------------- prep kernels ----------------
__global__ void prep_z_kernel(const float* __restrict__ z) {
    int b = blockIdx.x * blockDim.x + threadIdx.x;
    if (b >= NB) return;
    const float4* z4 = reinterpret_cast<const float4*>(z + b * NN);
    float s = 0.f;
    __nv_bfloat16* dst = g_zt + (b >> 7) * 4096 + (b & 127) * 32;
    #pragma unroll
    for (int i = 0; i < 8; i++) {
        float4 v = z4[i];
        s = fmaf(v.x, v.x, fmaf(v.y, v.y, fmaf(v.z, v.z, fmaf(v.w, v.w, s))));
        reinterpret_cast<uint2*>(dst)[i] =
            make_uint2(pk(__float2bfloat16(v.x), __float2bfloat16(v.y)),
                       pk(__float2bfloat16(v.z), __float2bfloat16(v.w)));
    }
    g_zn[b] = s;
}

__global__ void prep_w_kernel(const float* __restrict__ zj, const float* __restrict__ vd,
                              const float* __restrict__ alpha, const float* __restrict__ sp,
                              const float* __restrict__ spr) {
    __shared__ float zs[32][33], ds[32][33], invs[32];
    int grp = blockIdx.x, tid = threadIdx.x;       // 256 threads
    {   // coalesced stage: 32 m x 32 k
        int f = tid;                                // 1024 floats / 4 = 256 float4
        int mm = f >> 3, part = f & 7;
        float4 a = reinterpret_cast<const float4*>(zj + (size_t)(grp * 32 + mm) * NN)[part];
        float4 b = reinterpret_cast<const float4*>(vd + (size_t)(grp * 32 + mm) * NN)[part];
        zs[mm][part*4] = a.x; zs[mm][part*4+1] = a.y; zs[mm][part*4+2] = a.z; zs[mm][part*4+3] = a.w;
        ds[mm][part*4] = b.x; ds[mm][part*4+1] = b.y; ds[mm][part*4+2] = b.z; ds[mm][part*4+3] = b.w;
    }
    __syncthreads();
    if (tid < 32) {
        int m = grp * 32 + tid;
        float d2 = 0.f, zz = 0.f, cr = 0.f;
        #pragma unroll
        for (int k = 0; k < 32; k++) {
            float dv = ds[tid][k], zv = zs[tid][k];
            d2 = fmaf(dv, dv, d2); zz = fmaf(zv, zv, zz); cr = fmaf(zv, dv, cr);
        }
        float dn = sqrtf(d2);
        float inv = (dn > 1e-6f) ? (1.0f / dn) : 0.0f;
        invs[tid] = inv;
        const float tiny = 1.1920929e-7f;
        float a = fmaxf(sp[m], tiny), bb = fmaxf(spr[m], tiny);
        float wpar = 1.f / (a * a), wperp = 1.f / (bb * bb);
        g_par0[m] = make_float4(wperp, wperp * zz, -2.f * wperp, wpar - wperp);
        g_par1[m] = make_float2(cr * inv, alpha[m]);
    }
    __syncthreads();
    // write W [32 k][64 n] bf16: 2048 elems, 8 per thread
    int k = tid >> 3, c8 = (tid & 7) * 8;           // 8 consecutive n
    uint2 w;
    uint32_t o[4];
    #pragma unroll
    for (int j = 0; j < 4; j++) {
        int n0 = c8 + 2 * j, n1 = n0 + 1;
        float v0 = (n0 < 32) ? zs[n0][k] : ds[n0 - 32][k] * invs[n0 - 32];
        float v1 = (n1 < 32) ? zs[n1][k] : ds[n1 - 32][k] * invs[n1 - 32];
        o[j] = pk(__float2bfloat16(v0), __float2bfloat16(v1));
    }
    reinterpret_cast<uint4*>(g_WB + grp * 2048 + k * 64 + c8)[0] = make_uint4(o[0], o[1], o[2], o[3]);
    (void)w;
}

__global__ void prep_that_kernel(const float* __restrict__ that) {
    int grp = blockIdx.x, tid = threadIdx.x;        // 256 threads
    int m = tid >> 3, s0 = (tid & 7) * 16;
    const float4* src = reinterpret_cast<const float4*>(that + (size_t)(grp * 32 + m) * NS + s0);
    __nv_bfloat16* th = g_TB + (size_t)grp * 8192 + m * 128 + s0;
    __nv_bfloat16* tl = th + 32 * 128;
    #pragma unroll
    for (int i = 0; i < 4; i++) {
        float4 v = src[i];
        float f[4] = {v.x, v.y, v.z, v.w};
        #pragma unroll
        for (int j = 0; j < 4; j++) {
            __nv_bfloat16 h = __float2bfloat16(f[j]);
            th[i * 4 + j] = h;
            tl[i * 4 + j] = __float2bfloat16(f[j] - __bfloat162float(h));
        }
    }
}

// ---------------- fused mma.sync kernel ----------------
__global__ void __launch_bounds__(256, 2) fused_kernel() {
    __shared__ __align__(16) char smc[SM_TOT];
    const uint32_t sb = smem_u32(smc);
    const int tid = threadIdx.x, w = tid >> 5, lane = tid & 31;
    const int g = lane >> 2, t = lane & 3;
    const int mat = lane >> 3, lr = lane & 7;
    const int bb = blockIdx.x, ms = blockIdx.y, sh = blockIdx.z;

    {   // z tile once: [128][32] -> padded [128][40]
        const uint4* src = reinterpret_cast<const uint4*>(g_zt + bb * 4096);
        #pragma unroll
        for (int i = 0; i < 2; i++) {
            int idx = tid * 2 + i, r = idx >> 2, c = idx & 3;
            *reinterpret_cast<uint4*>(smc + SM_Z + r * 80 + c * 16) = src[idx];
        }
    }
    const float zn0 = g_zn[bb * 128 + w * 16 + g];
    const float zn1 = g_zn[bb * 128 + w * 16 + g + 8];

    float acc2[32];
    #pragma unroll
    for (int i = 0; i < 32; i++) acc2[i] = 0.f;

    for (int ch = 0; ch < NCHUNK; ch++) {
        const int grp = ms * NCHUNK + ch;
        __syncthreads();   // prior mma2 done reading B/A2 (and z copy on ch=0)
        {   // W copy: 256 uint4
            const uint4* ws = reinterpret_cast<const uint4*>(g_WB + grp * 2048);
            *reinterpret_cast<uint4*>(smc + SM_W + (tid >> 3) * 144 + (tid & 7) * 16) = ws[tid];
            // B copy: s-half slice [64][64]: 512 uint4
            const __nv_bfloat16* tsrc = g_TB + (size_t)grp * 8192 + sh * 64;
            #pragma unroll
            for (int i = 0; i < 2; i++) {
                int idx = tid + i * 256, r = idx >> 3, c = idx & 7;
                *reinterpret_cast<uint4*>(smc + SM_B + r * 144 + c * 16) =
                    *reinterpret_cast<const uint4*>(tsrc + r * 128 + c * 8);
            }
            if (tid < 32)
                reinterpret_cast<float4*>(smc + SM_P0)[tid] = g_par0[grp * 32 + tid];
            else if (tid < 64)
                reinterpret_cast<float2*>(smc + SM_P1)[tid - 32] = g_par1[grp * 32 + tid - 32];
        }
        __syncthreads();

        // ---- phase 1: U[16 rows x 64] = z x W ----
        float c1[32];
        #pragma unroll
        for (int i = 0; i < 32; i++) c1[i] = 0.f;
        #pragma unroll
        for (int kt = 0; kt < 2; kt++) {
            uint32_t a[4];
            ldsm4(a, lmaddr(sb + SM_Z, w * 16, kt * 16, 80, mat, lr));
            #pragma unroll
            for (int nt2 = 0; nt2 < 4; nt2++) {
                uint32_t b[4];
                ldsm4t(b, lmaddr(sb + SM_W, kt * 16, nt2 * 16, 144, mat, lr));
                mmabf(c1 + (nt2 * 2) * 4, a, b[0], b[1]);
                mmabf(c1 + (nt2 * 2 + 1) * 4, a, b[2], b[3]);
            }
        }
        // ---- epilogue: gains -> A2 [gh(0-31)|gl(32-63)] ----
        const int rowA = w * 16 + g;
        #pragma unroll
        for (int j = 0; j < 4; j++) {
            const int m0p = 8 * j + 2 * t;
            float4 pA = *reinterpret_cast<float4*>(smc + SM_P0 + m0p * 16);
            float4 pB = *reinterpret_cast<float4*>(smc + SM_P0 + (m0p + 1) * 16);
            float2 cA = *reinterpret_cast<float2*>(smc + SM_P1 + m0p * 8);
            float2 cB = *reinterpret_cast<float2*>(smc + SM_P1 + (m0p + 1) * 8);
            float gn[4];
            #pragma unroll
            for (int i = 0; i < 4; i++) {
                float u = c1[4 * j + i];
                float v = c1[(j + 4) * 4 + i];
                float zn = (i < 2) ? zn0 : zn1;
                float4 pp = (i & 1) ? pB : pA;
                float2 cc = (i & 1) ? cB : cA;
                float tq = v - cc.x;
                float q = fmaf(pp.x, zn, pp.y);
                q = fmaf(pp.z, u, q);
                q = fmaf(pp.w * tq, tq, q);
                q = fminf(q, 25.0f);
                gn[i] = cc.y * __expf(-PI_F * q);
            }
            __nv_bfloat16 h0 = __float2bfloat16(gn[0]), h1 = __float2bfloat16(gn[1]);
            __nv_bfloat16 h2 = __float2bfloat16(gn[2]), h3 = __float2bfloat16(gn[3]);
            char* r0 = smc + SM_A2 + rowA * 144;
            char* r1 = smc + SM_A2 + (rowA + 8) * 144;
            *reinterpret_cast<uint32_t*>(r0 + m0p * 2) = pk(h0, h1);
            *reinterpret_cast<uint32_t*>(r1 + m0p * 2) = pk(h2, h3);
            *reinterpret_cast<uint32_t*>(r0 + (32 + m0p) * 2) =
                pk(__float2bfloat16(gn[0] - __bfloat162float(h0)),
                   __float2bfloat16(gn[1] - __bfloat162float(h1)));
            *reinterpret_cast<uint32_t*>(r1 + (32 + m0p) * 2) =
                pk(__float2bfloat16(gn[2] - __bfloat162float(h2)),
                   __float2bfloat16(gn[3] - __bfloat162float(h3)));
        }
        __syncthreads();

        // ---- mma2: O += A2 x B, each B frag used with A[kt] and A[kt^2-ish] ----
        uint32_t af[4][4];
        #pragma unroll
        for (int kt = 0; kt < 4; kt++)
            ldsm4(af[kt], lmaddr(sb + SM_A2, w * 16, kt * 16, 144, mat, lr));
        #pragma unroll
        for (int kt = 0; kt < 4; kt++) {
            const int kt2 = (kt + 2) & 3;
            #pragma unroll
            for (int nt2 = 0; nt2 < 4; nt2++) {
                uint32_t b[4];
                ldsm4t(b, lmaddr(sb + SM_B, kt * 16, nt2 * 16, 144, mat, lr));
                mmabf(acc2 + (nt2 * 2) * 4,     af[kt],  b[0], b[1]);
                mmabf(acc2 + (nt2 * 2 + 1) * 4, af[kt],  b[2], b[3]);
                mmabf(acc2 + (nt2 * 2) * 4,     af[kt2], b[0], b[1]);
                mmabf(acc2 + (nt2 * 2 + 1) * 4, af[kt2], b[2], b[3]);
            }
        }
    }

    // write partials: [ms][b][s], s-half offset
    float* op = g_part + ((size_t)ms * NB + bb * 128 + w * 16) * NS + sh * 64;
    #pragma unroll
    for (int j = 0; j < 8; j++) {
        *reinterpret_cast<float2*>(op + g * NS + j * 8 + 2 * t) =
            make_float2(acc2[4 * j], acc2[4 * j + 1]);
        *reinterpret_cast<float2*>(op + (g + 8) * NS + j * 8 + 2 * t) =
            make_float2(acc2[4 * j + 2], acc2[4 * j + 3]);
    }
}

__global__ void reduce_kernel(float* __restrict__ out) {
    int idx = blockIdx.x * blockDim.x + threadIdx.x;   // B*S/4 threads
    const float4* gp = reinterpret_cast<const float4*>(g_part);
    const size_t stride = (size_t)NB * NS / 4;
    float4 a0 = {0,0,0,0}, a1 = {0,0,0,0};
    #pragma unroll
    for (int p = 0; p < 8; p++) {
        float4 v0 = gp[(2 * p) * stride + idx];
        float4 v1 = gp[(2 * p + 1) * stride + idx];
        a0.x += v0.x; a0.y += v0.y; a0.z += v0.z; a0.w += v0.w;
        a1.x += v1.x; a1.y += v1.y; a1.z += v1.z; a1.w += v1.w;
    }
    a0.x += a1.x; a0.y += a1.y; a0.z += a1.z; a0.w += a1.w;
    reinterpret_cast<float4*>(out)[idx] = a0;
}

extern "C" void kernel_launch(void* const* d_in, const int* in_sizes, int n_in,
                              void* d_out, int out_size) {
    const float* z     = (const float*)d_in[0];
    const float* zj    = (const float*)d_in[1];
    const float* vd    = (const float*)d_in[2];
    const float* that  = (const float*)d_in[3];
    const float* alpha = (const float*)d_in[4];
    const float* sp    = (const float*)d_in[5];
    const float* spr   = (const float*)d_in[6];
    float* out = (float*)d_out;

    prep_z_kernel<<<(NB + 255) / 256, 256>>>(z);
    prep_w_kernel<<<NGRP, 256>>>(zj, vd, alpha, sp, spr);
    prep_that_kernel<<<NGRP, 256>>>(that);
    fused_kernel<<<dim3(NB / 128, MSPLIT, 2), 256>>>();
    reduce_kernel<<<(NB * NS / 4) / 256, 256>>>(out);
}

// round 12
// speedup vs baseline: 1.7428x; 1.2478x over previous
#include <cuda_runtime.h>
#include <cuda_bf16.h>
#include <cstdint>

#define NB 1024
#define NM 8192
#define NN 32
#define NS 128
#define MSPLIT 16
#define NCHUNK 16
#define NGRP 256
#define PI_F 3.14159265358979f

// static smem: z tile + 2 double-buffered (W|B|par) stages
#define SM_Z    0          // [128][40] bf16 (stride 80B) = 10240
#define SM_BUF  10240
#define BUF_SZ  14592      // W 4608 | B 9216 | P0 512 | P1 256
#define BO_W    0          // [32][72] bf16 stride 144B
#define BO_B    4608       // [64][72] bf16 stride 144B
#define BO_P0   13824
#define BO_P1   14336
#define SM_TOT  (SM_BUF + 2 * BUF_SZ)   // 39424

__device__ __nv_bfloat16 g_zt[8 * 128 * 32];
__device__ float         g_zn[NB];
__device__ __nv_bfloat16 g_WB[NGRP * 32 * 64];     // per grp [32 k][64 n] (n: 0-31 zj, 32-63 bhat)
__device__ __nv_bfloat16 g_TB[NGRP * 64 * 128];    // per grp [64 k][128 s] (k: 0-31 th, 32-63 tl)
__device__ float4        g_par0[NM];
__device__ float2        g_par1[NM];
__device__ float         g_part[(size_t)MSPLIT * NB * NS];

__device__ __forceinline__ uint32_t smem_u32(const void* p) {
    uint32_t a;
    asm("{ .reg .u64 t; cvta.to.shared.u64 t, %1; cvt.u32.u64 %0, t; }" : "=r"(a) : "l"(p));
    return a;
}
__device__ __forceinline__ void ldsm4(uint32_t* r, uint32_t a) {
    asm volatile("ldmatrix.sync.aligned.m8n8.x4.shared.b16 {%0,%1,%2,%3}, [%4];"
        : "=r"(r[0]), "=r"(r[1]), "=r"(r[2]), "=r"(r[3]) : "r"(a));
}
__device__ __forceinline__ void ldsm4t(uint32_t* r, uint32_t a) {
    asm volatile("ldmatrix.sync.aligned.m8n8.x4.trans.shared.b16 {%0,%1,%2,%3}, [%4];"
        : "=r"(r[0]), "=r"(r[1]), "=r"(r[2]), "=r"(r[3]) : "r"(a));
}
__device__ __forceinline__ void mmabf(float* c, const uint32_t* a, uint32_t b0, uint32_t b1) {
    asm volatile("mma.sync.aligned.m16n8k16.row.col.f32.bf16.bf16.f32 "
        "{%0,%1,%2,%3}, {%4,%5,%6,%7}, {%8,%9}, {%0,%1,%2,%3};"
        : "+f"(c[0]), "+f"(c[1]), "+f"(c[2]), "+f"(c[3])
        : "r"(a[0]), "r"(a[1]), "r"(a[2]), "r"(a[3]), "r"(b0), "r"(b1));
}
__device__ __forceinline__ uint32_t lmaddr(uint32_t base, int rowB, int colB, int strideB,
                                           int mat, int lr) {
    return base + (uint32_t)((rowB + lr + 8 * (mat & 1)) * strideB + (colB + 8 * (mat >> 1)) * 2);
}
__device__ __forceinline__ uint32_t pk(__nv_bfloat16 a, __nv_bfloat16 b) {
    __nv_bfloat162 t; t.x = a; t.y = b;
    return *reinterpret_cast<uint32_t*>(&t);
}
#define CPA16(d, s) asm volatile("cp.async.cg.shared.global [%0], [%1], 16;" :: "r"(d), "l"(s) : "memory")
#define CPA8(d, s)  asm volatile("cp.async.ca.shared.global [%0], [%1], 8;"  :: "r"(d), "l"(s) : "memory")
#define CPCOMMIT()  asm volatile("cp.async.commit_group;" ::: "memory")
#define CPWAIT0()   asm volatile("cp.async.wait_group 0;" ::: "memory")

// ---------------- prep kernels ----------------
__global__ void prep_z_kernel(const float* __restrict__ z) {
    int b = blockIdx.x * blockDim.x + threadIdx.x;
    if (b >= NB) return;
    const float4* z4 = reinterpret_cast<const float4*>(z + b * NN);
    float s = 0.f;
    __nv_bfloat16* dst = g_zt + (b >> 7) * 4096 + (b & 127) * 32;
    #pragma unroll
    for (int i = 0; i < 8; i++) {
        float4 v = z4[i];
        s = fmaf(v.x, v.x, fmaf(v.y, v.y, fmaf(v.z, v.z, fmaf(v.w, v.w, s))));
        reinterpret_cast<uint2*>(dst)[i] =
            make_uint2(pk(__float2bfloat16(v.x), __float2bfloat16(v.y)),
                       pk(__float2bfloat16(v.z), __float2bfloat16(v.w)));
    }
    g_zn[b] = s;
}

__global__ void prep_m_kernel(const float* __restrict__ zj, const float* __restrict__ vd,
                              const float* __restrict__ alpha, const float* __restrict__ sp,
                              const float* __restrict__ spr, const float* __restrict__ that) {
    __shared__ float zs[32][33], ds[32][33], invs[32];
    int grp = blockIdx.x, tid = threadIdx.x;       // 256 threads
    {
        int mm = tid >> 3, part = tid & 7;
        float4 a = reinterpret_cast<const float4*>(zj + (size_t)(grp * 32 + mm) * NN)[part];
        float4 b = reinterpret_cast<const float4*>(vd + (size_t)(grp * 32 + mm) * NN)[part];
        zs[mm][part*4] = a.x; zs[mm][part*4+1] = a.y; zs[mm][part*4+2] = a.z; zs[mm][part*4+3] = a.w;
        ds[mm][part*4] = b.x; ds[mm][part*4+1] = b.y; ds[mm][part*4+2] = b.z; ds[mm][part*4+3] = b.w;
    }
    // T_hat split (independent of the staged data)
    {
        int m = tid >> 3, s0 = (tid & 7) * 16;
        const float4* src = reinterpret_cast<const float4*>(that + (size_t)(grp * 32 + m) * NS + s0);
        __nv_bfloat16* th = g_TB + (size_t)grp * 8192 + m * 128 + s0;
        __nv_bfloat16* tl = th + 32 * 128;
        #pragma unroll
        for (int i = 0; i < 4; i++) {
            float4 v = src[i];
            float f[4] = {v.x, v.y, v.z, v.w};
            #pragma unroll
            for (int j = 0; j < 4; j++) {
                __nv_bfloat16 h = __float2bfloat16(f[j]);
                th[i * 4 + j] = h;
                tl[i * 4 + j] = __float2bfloat16(f[j] - __bfloat162float(h));
            }
        }
    }
    __syncthreads();
    if (tid < 32) {
        int m = grp * 32 + tid;
        float d2 = 0.f, zz = 0.f, cr = 0.f;
        #pragma unroll
        for (int k = 0; k < 32; k++) {
            float dv = ds[tid][k], zv = zs[tid][k];
            d2 = fmaf(dv, dv, d2); zz = fmaf(zv, zv, zz); cr = fmaf(zv, dv, cr);
        }
        float dn = sqrtf(d2);
        float inv = (dn > 1e-6f) ? (1.0f / dn) : 0.0f;
        invs[tid] = inv;
        const float tiny = 1.1920929e-7f;
        float a = fmaxf(sp[m], tiny), bb = fmaxf(spr[m], tiny);
        float wpar = 1.f / (a * a), wperp = 1.f / (bb * bb);
        g_par0[m] = make_float4(wperp, wperp * zz, -2.f * wperp, wpar - wperp);
        g_par1[m] = make_float2(cr * inv, alpha[m]);
    }
    __syncthreads();
    int k = tid >> 3, c8 = (tid & 7) * 8;
    uint32_t o[4];
    #pragma unroll
    for (int j = 0; j < 4; j++) {
        int n0 = c8 + 2 * j, n1 = n0 + 1;
        float v0 = (n0 < 32) ? zs[n0][k] : ds[n0 - 32][k] * invs[n0 - 32];
        float v1 = (n1 < 32) ? zs[n1][k] : ds[n1 - 32][k] * invs[n1 - 32];
        o[j] = pk(__float2bfloat16(v0), __float2bfloat16(v1));
    }
    reinterpret_cast<uint4*>(g_WB + grp * 2048 + k * 64 + c8)[0] = make_uint4(o[0], o[1], o[2], o[3]);
}

// ---------------- fused kernel: gains stay in registers as A-fragments ----------------
__global__ void __launch_bounds__(256, 2) fused_kernel() {
    __shared__ __align__(16) char smc[SM_TOT];
    const uint32_t sb = smem_u32(smc);
    const int tid = threadIdx.x, w = tid >> 5, lane = tid & 31;
    const int g = lane >> 2, t = lane & 3;
    const int mat = lane >> 3, lr = lane & 7;
    const int bb = blockIdx.x, ms = blockIdx.y, sh = blockIdx.z;

    // prefetch helper targets
    const int wr = tid >> 3, wc = tid & 7;

    {   // z tile: [128][32] -> padded [128][40]
        const uint4* src = reinterpret_cast<const uint4*>(g_zt + bb * 4096);
        #pragma unroll
        for (int i = 0; i < 2; i++) {
            int idx = tid * 2 + i, r = idx >> 2, c = idx & 3;
            *reinterpret_cast<uint4*>(smc + SM_Z + r * 80 + c * 16) = src[idx];
        }
    }
    // prefetch chunk 0
    {
        const int grp = ms * NCHUNK;
        uint32_t bd = sb + SM_BUF;
        CPA16(bd + BO_W + wr * 144 + wc * 16, g_WB + grp * 2048 + wr * 64 + wc * 8);
        #pragma unroll
        for (int i = 0; i < 2; i++) {
            int o = tid + i * 256, r = o >> 3, c = o & 7;
            CPA16(bd + BO_B + r * 144 + c * 16, g_TB + (size_t)grp * 8192 + sh * 64 + r * 128 + c * 8);
        }
        if (tid < 32)      CPA16(bd + BO_P0 + tid * 16, g_par0 + grp * 32 + tid);
        else if (tid < 64) CPA8(bd + BO_P1 + (tid - 32) * 8, g_par1 + grp * 32 + tid - 32);
        CPCOMMIT();
    }
    __syncthreads();   // z tile visible
    uint32_t az[2][4];
    ldsm4(az[0], lmaddr(sb + SM_Z, w * 16, 0, 80, mat, lr));
    ldsm4(az[1], lmaddr(sb + SM_Z, w * 16, 16, 80, mat, lr));

    const float zn0 = g_zn[bb * 128 + w * 16 + g];
    const float zn1 = g_zn[bb * 128 + w * 16 + g + 8];

    float acc2[32];
    #pragma unroll
    for (int i = 0; i < 32; i++) acc2[i] = 0.f;

    for (int ch = 0; ch < NCHUNK; ch++) {
        const uint32_t bd = sb + SM_BUF + (ch & 1) * BUF_SZ;
        CPWAIT0();
        __syncthreads();          // buffer(ch) ready for all; compute(ch-1) done for all
        if (ch + 1 < NCHUNK) {    // prefetch next into other buffer
            const int grp = ms * NCHUNK + ch + 1;
            uint32_t nd = sb + SM_BUF + ((ch + 1) & 1) * BUF_SZ;
            CPA16(nd + BO_W + wr * 144 + wc * 16, g_WB + grp * 2048 + wr * 64 + wc * 8);
            #pragma unroll
            for (int i = 0; i < 2; i++) {
                int o = tid + i * 256, r = o >> 3, c = o & 7;
                CPA16(nd + BO_B + r * 144 + c * 16,
                      g_TB + (size_t)grp * 8192 + sh * 64 + r * 128 + c * 8);
            }
            if (tid < 32)      CPA16(nd + BO_P0 + tid * 16, g_par0 + grp * 32 + tid);
            else if (tid < 64) CPA8(nd + BO_P1 + (tid - 32) * 8, g_par1 + grp * 32 + tid - 32);
            CPCOMMIT();
        }

        // ---- phase 1: U[16 x 64] = z x W ----
        float c1[32];
        #pragma unroll
        for (int i = 0; i < 32; i++) c1[i] = 0.f;
        #pragma unroll
        for (int kt = 0; kt < 2; kt++) {
            #pragma unroll
            for (int nt2 = 0; nt2 < 4; nt2++) {
                uint32_t b[4];
                ldsm4t(b, lmaddr(bd + BO_W, kt * 16, nt2 * 16, 144, mat, lr));
                mmabf(c1 + nt2 * 8,     az[kt], b[0], b[1]);
                mmabf(c1 + nt2 * 8 + 4, az[kt], b[2], b[3]);
            }
        }

        // ---- epilogue in registers: gains -> A-fragments (hi & lo) ----
        uint32_t afh[2][4], afl[2][4];
        #pragma unroll
        for (int j = 0; j < 4; j++) {
            const int m0p = 8 * j + 2 * t;
            float4 pA = *reinterpret_cast<float4*>(smc + (bd - sb) + BO_P0 + m0p * 16);
            float4 pB = *reinterpret_cast<float4*>(smc + (bd - sb) + BO_P0 + (m0p + 1) * 16);
            float2 cA = *reinterpret_cast<float2*>(smc + (bd - sb) + BO_P1 + m0p * 8);
            float2 cB = *reinterpret_cast<float2*>(smc + (bd - sb) + BO_P1 + (m0p + 1) * 8);
            float gn[4];
            #pragma unroll
            for (int i = 0; i < 4; i++) {
                float u = c1[4 * j + i];
                float v = c1[(j + 4) * 4 + i];
                float zn = (i < 2) ? zn0 : zn1;
                float4 pp = (i & 1) ? pB : pA;
                float2 cc = (i & 1) ? cB : cA;
                float tq = v - cc.x;
                float q = fmaf(pp.x, zn, pp.y);
                q = fmaf(pp.z, u, q);
                q = fmaf(pp.w * tq, tq, q);
                q = fminf(q, 25.0f);
                gn[i] = cc.y * __expf(-PI_F * q);
            }
            __nv_bfloat16 h0 = __float2bfloat16(gn[0]), h1 = __float2bfloat16(gn[1]);
            __nv_bfloat16 h2 = __float2bfloat16(gn[2]), h3 = __float2bfloat16(gn[3]);
            const int kt = j >> 1, o = (j & 1) * 2;
            afh[kt][o]     = pk(h0, h1);
            afh[kt][o + 1] = pk(h2, h3);
            afl[kt][o]     = pk(__float2bfloat16(gn[0] - __bfloat162float(h0)),
                                __float2bfloat16(gn[1] - __bfloat162float(h1)));
            afl[kt][o + 1] = pk(__float2bfloat16(gn[2] - __bfloat162float(h2)),
                                __float2bfloat16(gn[3] - __bfloat162float(h3)));
        }

        // ---- mma2: O += g x that, 3 split terms (gh*th, gl*th, gh*tl) ----
        #pragma unroll
        for (int ktile = 0; ktile < 4; ktile++) {
            const int kk = ktile & 1;   // th blocks: ktile 0,1 (m halves); tl: 2,3
            #pragma unroll
            for (int nt2 = 0; nt2 < 4; nt2++) {
                uint32_t b[4];
                ldsm4t(b, lmaddr(bd + BO_B, ktile * 16, nt2 * 16, 144, mat, lr));
                mmabf(acc2 + nt2 * 8,     afh[kk], b[0], b[1]);
                mmabf(acc2 + nt2 * 8 + 4, afh[kk], b[2], b[3]);
                if (ktile < 2) {
                    mmabf(acc2 + nt2 * 8,     afl[kk], b[0], b[1]);
                    mmabf(acc2 + nt2 * 8 + 4, afl[kk], b[2], b[3]);
                }
            }
        }
    }

    // write partials: [ms][b][s]
    float* op = g_part + ((size_t)ms * NB + bb * 128 + w * 16) * NS + sh * 64;
    #pragma unroll
    for (int j = 0; j < 8; j++) {
        *reinterpret_cast<float2*>(op + g * NS + j * 8 + 2 * t) =
            make_float2(acc2[4 * j], acc2[4 * j + 1]);
        *reinterpret_cast<float2*>(op + (g + 8) * NS + j * 8 + 2 * t) =
            make_float2(acc2[4 * j + 2], acc2[4 * j + 3]);
    }
}

__global__ void reduce_kernel(float* __restrict__ out) {
    int idx = blockIdx.x * blockDim.x + threadIdx.x;   // B*S/4 threads
    const float4* gp = reinterpret_cast<const float4*>(g_part);
    const size_t stride = (size_t)NB * NS / 4;
    float4 a0 = {0,0,0,0}, a1 = {0,0,0,0}, a2 = {0,0,0,0}, a3 = {0,0,0,0};
    #pragma unroll
    for (int p = 0; p < 4; p++) {
        float4 v0 = gp[(4 * p + 0) * stride + idx];
        float4 v1 = gp[(4 * p + 1) * stride + idx];
        float4 v2 = gp[(4 * p + 2) * stride + idx];
        float4 v3 = gp[(4 * p + 3) * stride + idx];
        a0.x += v0.x; a0.y += v0.y; a0.z += v0.z; a0.w += v0.w;
        a1.x += v1.x; a1.y += v1.y; a1.z += v1.z; a1.w += v1.w;
        a2.x += v2.x; a2.y += v2.y; a2.z += v2.z; a2.w += v2.w;
        a3.x += v3.x; a3.y += v3.y; a3.z += v3.z; a3.w += v3.w;
    }
    a0.x += a1.x + a2.x + a3.x; a0.y += a1.y + a2.y + a3.y;
    a0.z += a1.z + a2.z + a3.z; a0.w += a1.w + a2.w + a3.w;
    reinterpret_cast<float4*>(out)[idx] = a0;
}

extern "C" void kernel_launch(void* const* d_in, const int* in_sizes, int n_in,
                              void* d_out, int out_size) {
    const float* z     = (const float*)d_in[0];
    const float* zj    = (const float*)d_in[1];
    const float* vd    = (const float*)d_in[2];
    const float* that  = (const float*)d_in[3];
    const float* alpha = (const float*)d_in[4];
    const float* sp    = (const float*)d_in[5];
    const float* spr   = (const float*)d_in[6];
    float* out = (float*)d_out;

    prep_z_kernel<<<4, 256>>>(z);
    prep_m_kernel<<<NGRP, 256>>>(zj, vd, alpha, sp, spr, that);
    fused_kernel<<<dim3(NB / 128, MSPLIT, 2), 256>>>();
    reduce_kernel<<<256, 128>>>(out);
}

// round 13
// speedup vs baseline: 1.7438x; 1.0006x over previous
#include <cuda_runtime.h>
#include <cuda_bf16.h>
#include <cstdint>

#define NB 1024
#define NM 8192
#define NN 32
#define NS 128
#define MSPLIT 16
#define NCHUNK 16
#define NGRP 256
#define NEG_PI_LN2 (-4.532360141827194f)
#define QCLAMP (-113.3090035456798f)

// smem: A2/z region (A2 [128][144B] = 18432; z staged first as [128][80B]) + 2 buffers
#define SM_A2Z 0
#define SM_BUF 18432
#define BUF_SZ 14592       // W 4608 | B 9216 | P0 512 | P1 256
#define BO_W   0           // [32][72] bf16 stride 144B
#define BO_B   4608        // [64][72] bf16 stride 144B
#define BO_P0  13824
#define BO_P1  14336
#define SM_TOT (SM_BUF + 2 * BUF_SZ)   // 47616 (< 48KB static)

__device__ __nv_bfloat16 g_zt[8 * 128 * 32];
__device__ float         g_zn[NB];
__device__ __nv_bfloat16 g_WB[NGRP * 32 * 64];   // [32 k][64 n] (n: 0-31 zj, 32-63 bhat)
__device__ __nv_bfloat16 g_TB[NGRP * 64 * 128];  // [64 k][128 s] (k: 0-31 th, 32-63 tl)
__device__ float4        g_par0[NM];             // pre-scaled by -pi/ln2
__device__ float2        g_par1[NM];             // {c, alpha}
__device__ float         g_part[(size_t)MSPLIT * NB * NS];

__device__ __forceinline__ uint32_t smem_u32(const void* p) {
    uint32_t a;
    asm("{ .reg .u64 t; cvta.to.shared.u64 t, %1; cvt.u32.u64 %0, t; }" : "=r"(a) : "l"(p));
    return a;
}
__device__ __forceinline__ void ldsm4(uint32_t* r, uint32_t a) {
    asm volatile("ldmatrix.sync.aligned.m8n8.x4.shared.b16 {%0,%1,%2,%3}, [%4];"
        : "=r"(r[0]), "=r"(r[1]), "=r"(r[2]), "=r"(r[3]) : "r"(a));
}
__device__ __forceinline__ void ldsm4t(uint32_t* r, uint32_t a) {
    asm volatile("ldmatrix.sync.aligned.m8n8.x4.trans.shared.b16 {%0,%1,%2,%3}, [%4];"
        : "=r"(r[0]), "=r"(r[1]), "=r"(r[2]), "=r"(r[3]) : "r"(a));
}
__device__ __forceinline__ void mmabf(float* c, const uint32_t* a, uint32_t b0, uint32_t b1) {
    asm volatile("mma.sync.aligned.m16n8k16.row.col.f32.bf16.bf16.f32 "
        "{%0,%1,%2,%3}, {%4,%5,%6,%7}, {%8,%9}, {%0,%1,%2,%3};"
        : "+f"(c[0]), "+f"(c[1]), "+f"(c[2]), "+f"(c[3])
        : "r"(a[0]), "r"(a[1]), "r"(a[2]), "r"(a[3]), "r"(b0), "r"(b1));
}
__device__ __forceinline__ uint32_t lmaddr(uint32_t base, int rowB, int colB, int strideB,
                                           int mat, int lr) {
    return base + (uint32_t)((rowB + lr + 8 * (mat & 1)) * strideB + (colB + 8 * (mat >> 1)) * 2);
}
__device__ __forceinline__ uint32_t pk(__nv_bfloat16 a, __nv_bfloat16 b) {
    __nv_bfloat162 t; t.x = a; t.y = b;
    return *reinterpret_cast<uint32_t*>(&t);
}
__device__ __forceinline__ float ex2f(float x) {
    float r; asm("ex2.approx.f32 %0, %1;" : "=f"(r) : "f"(x)); return r;
}
#define CPA16(d, s) asm volatile("cp.async.cg.shared.global [%0], [%1], 16;" :: "r"(d), "l"(s) : "memory")
#define CPA8(d, s)  asm volatile("cp.async.ca.shared.global [%0], [%1], 8;"  :: "r"(d), "l"(s) : "memory")
#define CPCOMMIT()  asm volatile("cp.async.commit_group;" ::: "memory")
#define CPWAIT0()   asm volatile("cp.async.wait_group 0;" ::: "memory")
#define BARS(id, n) asm volatile("bar.sync %0, %1;" :: "r"(id), "r"(n) : "memory")
#define BARA(id, n) asm volatile("bar.arrive %0, %1;" :: "r"(id), "r"(n) : "memory")

// ---------------- prep kernels ----------------
__global__ void prep_z_kernel(const float* __restrict__ z) {
    int b = blockIdx.x * blockDim.x + threadIdx.x;
    if (b >= NB) return;
    const float4* z4 = reinterpret_cast<const float4*>(z + b * NN);
    float s = 0.f;
    __nv_bfloat16* dst = g_zt + (b >> 7) * 4096 + (b & 127) * 32;
    #pragma unroll
    for (int i = 0; i < 8; i++) {
        float4 v = z4[i];
        s = fmaf(v.x, v.x, fmaf(v.y, v.y, fmaf(v.z, v.z, fmaf(v.w, v.w, s))));
        reinterpret_cast<uint2*>(dst)[i] =
            make_uint2(pk(__float2bfloat16(v.x), __float2bfloat16(v.y)),
                       pk(__float2bfloat16(v.z), __float2bfloat16(v.w)));
    }
    g_zn[b] = s;
}

__global__ void prep_m_kernel(const float* __restrict__ zj, const float* __restrict__ vd,
                              const float* __restrict__ alpha, const float* __restrict__ sp,
                              const float* __restrict__ spr, const float* __restrict__ that) {
    __shared__ float zs[32][33], ds[32][33], invs[32];
    int grp = blockIdx.x, tid = threadIdx.x;
    {
        int mm = tid >> 3, part = tid & 7;
        float4 a = reinterpret_cast<const float4*>(zj + (size_t)(grp * 32 + mm) * NN)[part];
        float4 b = reinterpret_cast<const float4*>(vd + (size_t)(grp * 32 + mm) * NN)[part];
        zs[mm][part*4] = a.x; zs[mm][part*4+1] = a.y; zs[mm][part*4+2] = a.z; zs[mm][part*4+3] = a.w;
        ds[mm][part*4] = b.x; ds[mm][part*4+1] = b.y; ds[mm][part*4+2] = b.z; ds[mm][part*4+3] = b.w;
    }
    {   // T_hat hi/lo split
        int m = tid >> 3, s0 = (tid & 7) * 16;
        const float4* src = reinterpret_cast<const float4*>(that + (size_t)(grp * 32 + m) * NS + s0);
        __nv_bfloat16* th = g_TB + (size_t)grp * 8192 + m * 128 + s0;
        __nv_bfloat16* tl = th + 32 * 128;
        #pragma unroll
        for (int i = 0; i < 4; i++) {
            float4 v = src[i];
            float f[4] = {v.x, v.y, v.z, v.w};
            #pragma unroll
            for (int j = 0; j < 4; j++) {
                __nv_bfloat16 h = __float2bfloat16(f[j]);
                th[i * 4 + j] = h;
                tl[i * 4 + j] = __float2bfloat16(f[j] - __bfloat162float(h));
            }
        }
    }
    __syncthreads();
    if (tid < 32) {
        int m = grp * 32 + tid;
        float d2 = 0.f, zz = 0.f, cr = 0.f;
        #pragma unroll
        for (int k = 0; k < 32; k++) {
            float dv = ds[tid][k], zv = zs[tid][k];
            d2 = fmaf(dv, dv, d2); zz = fmaf(zv, zv, zz); cr = fmaf(zv, dv, cr);
        }
        float dn = sqrtf(d2);
        float inv = (dn > 1e-6f) ? (1.0f / dn) : 0.0f;
        invs[tid] = inv;
        const float tiny = 1.1920929e-7f;
        float a = fmaxf(sp[m], tiny), bb = fmaxf(spr[m], tiny);
        float wpar = 1.f / (a * a), wperp = 1.f / (bb * bb);
        // pre-scaled by -pi/ln2: gain = alpha * ex2(q'')
        g_par0[m] = make_float4(NEG_PI_LN2 * wperp, NEG_PI_LN2 * wperp * zz,
                                NEG_PI_LN2 * -2.f * wperp, NEG_PI_LN2 * (wpar - wperp));
        g_par1[m] = make_float2(cr * inv, alpha[m]);
    }
    __syncthreads();
    int k = tid >> 3, c8 = (tid & 7) * 8;
    uint32_t o[4];
    #pragma unroll
    for (int j = 0; j < 4; j++) {
        int n0 = c8 + 2 * j, n1 = n0 + 1;
        float v0 = (n0 < 32) ? zs[n0][k] : ds[n0 - 32][k] * invs[n0 - 32];
        float v1 = (n1 < 32) ? zs[n1][k] : ds[n1 - 32][k] * invs[n1 - 32];
        o[j] = pk(__float2bfloat16(v0), __float2bfloat16(v1));
    }
    reinterpret_cast<uint4*>(g_WB + grp * 2048 + k * 64 + c8)[0] = make_uint4(o[0], o[1], o[2], o[3]);
}

// ---------------- warp-specialized fused kernel ----------------
__global__ void __launch_bounds__(256, 2) fused_kernel() {
    __shared__ __align__(16) char smc[SM_TOT];
    const uint32_t sb = smem_u32(smc);
    const int tid = threadIdx.x, lane = tid & 31;
    const int g = lane >> 2, t = lane & 3;
    const int mat = lane >> 3, lr = lane & 7;
    const int bb = blockIdx.x, ms = blockIdx.y, sh = blockIdx.z;

    if (tid < 128) {
        // ================= PRODUCER warps 0-3: gains =================
        const int ptid = tid, pw = tid >> 5;
        // initial prefetch W/par(0)
        {
            const int grp = ms * NCHUNK;
            uint32_t nd = sb + SM_BUF;
            #pragma unroll
            for (int i = 0; i < 2; i++) {
                int o = ptid + i * 128, r = o >> 3, c = o & 7;
                CPA16(nd + BO_W + r * 144 + c * 16, g_WB + grp * 2048 + r * 64 + c * 8);
            }
            if (ptid < 32)      CPA16(nd + BO_P0 + ptid * 16, g_par0 + grp * 32 + ptid);
            else if (ptid < 64) CPA8(nd + BO_P1 + (ptid - 32) * 8, g_par1 + grp * 32 + ptid - 32);
            CPCOMMIT();
        }
        // stage z into A2 region ([128][80B]) and extract A-frags
        {
            const uint4* zs = reinterpret_cast<const uint4*>(g_zt) + bb * 512;
            #pragma unroll
            for (int i = 0; i < 4; i++) {
                int o = ptid + i * 128, r = o >> 2, c = o & 3;
                *reinterpret_cast<uint4*>(smc + SM_A2Z + r * 80 + c * 16) = zs[o];
            }
        }
        BARS(5, 128);
        uint32_t az[2][2][4];
        float zn[2][2];
        #pragma unroll
        for (int rg = 0; rg < 2; rg++) {
            #pragma unroll
            for (int kt = 0; kt < 2; kt++)
                ldsm4(az[rg][kt], lmaddr(sb + SM_A2Z, pw * 32 + rg * 16, kt * 16, 80, mat, lr));
            zn[rg][0] = g_zn[bb * 128 + pw * 32 + rg * 16 + g];
            zn[rg][1] = g_zn[bb * 128 + pw * 32 + rg * 16 + g + 8];
        }
        BARS(5, 128);   // all az extracted before A2 region is overwritten

        for (int ch = 0; ch < NCHUNK; ch++) {
            const uint32_t bd = sb + SM_BUF + (ch & 1) * BUF_SZ;
            CPWAIT0();
            BARS(5, 128);                     // whole buffer(ch) landed; buf(ch-1) reads done
            if (ch + 1 < NCHUNK) {
                const int grp = ms * NCHUNK + ch + 1;
                uint32_t nd = sb + SM_BUF + ((ch + 1) & 1) * BUF_SZ;
                #pragma unroll
                for (int i = 0; i < 2; i++) {
                    int o = ptid + i * 128, r = o >> 3, c = o & 7;
                    CPA16(nd + BO_W + r * 144 + c * 16, g_WB + grp * 2048 + r * 64 + c * 8);
                }
                if (ptid < 32)      CPA16(nd + BO_P0 + ptid * 16, g_par0 + grp * 32 + ptid);
                else if (ptid < 64) CPA8(nd + BO_P1 + (ptid - 32) * 8, g_par1 + grp * 32 + ptid - 32);
                CPCOMMIT();
            }
            uint32_t wf[8][4];
            #pragma unroll
            for (int kt = 0; kt < 2; kt++)
                #pragma unroll
                for (int nt2 = 0; nt2 < 4; nt2++)
                    ldsm4t(wf[kt * 4 + nt2], lmaddr(bd + BO_W, kt * 16, nt2 * 16, 144, mat, lr));

            #pragma unroll
            for (int rg = 0; rg < 2; rg++) {
                float c1[32];
                #pragma unroll
                for (int i = 0; i < 32; i++) c1[i] = 0.f;
                #pragma unroll
                for (int kt = 0; kt < 2; kt++)
                    #pragma unroll
                    for (int nt2 = 0; nt2 < 4; nt2++) {
                        mmabf(c1 + nt2 * 8,     az[rg][kt], wf[kt*4+nt2][0], wf[kt*4+nt2][1]);
                        mmabf(c1 + nt2 * 8 + 4, az[rg][kt], wf[kt*4+nt2][2], wf[kt*4+nt2][3]);
                    }
                if (rg == 0 && ch > 0) BARS(2, 256);   // A2(ch-1) consumed by all consumers
                const int rowA = pw * 32 + rg * 16 + g;
                #pragma unroll
                for (int j = 0; j < 4; j++) {
                    const int m0p = 8 * j + 2 * t;
                    float4 pA = *reinterpret_cast<float4*>(smc + (bd - sb) + BO_P0 + m0p * 16);
                    float4 pB = *reinterpret_cast<float4*>(smc + (bd - sb) + BO_P0 + (m0p + 1) * 16);
                    float2 cA = *reinterpret_cast<float2*>(smc + (bd - sb) + BO_P1 + m0p * 8);
                    float2 cB = *reinterpret_cast<float2*>(smc + (bd - sb) + BO_P1 + (m0p + 1) * 8);
                    float gn[4];
                    #pragma unroll
                    for (int i = 0; i < 4; i++) {
                        float u = c1[4 * j + i];
                        float v = c1[(j + 4) * 4 + i];
                        float znv = zn[rg][i >> 1];
                        float4 pp = (i & 1) ? pB : pA;
                        float2 cc = (i & 1) ? cB : cA;
                        float tq = v - cc.x;
                        float q = fmaf(pp.x, znv, pp.y);
                        q = fmaf(pp.z, u, q);
                        q = fmaf(pp.w * tq, tq, q);
                        q = fmaxf(q, QCLAMP);
                        gn[i] = cc.y * ex2f(q);
                    }
                    __nv_bfloat16 h0 = __float2bfloat16(gn[0]), h1 = __float2bfloat16(gn[1]);
                    __nv_bfloat16 h2 = __float2bfloat16(gn[2]), h3 = __float2bfloat16(gn[3]);
                    char* r0 = smc + SM_A2Z + rowA * 144;
                    char* r1 = smc + SM_A2Z + (rowA + 8) * 144;
                    *reinterpret_cast<uint32_t*>(r0 + m0p * 2) = pk(h0, h1);
                    *reinterpret_cast<uint32_t*>(r1 + m0p * 2) = pk(h2, h3);
                    *reinterpret_cast<uint32_t*>(r0 + (32 + m0p) * 2) =
                        pk(__float2bfloat16(gn[0] - __bfloat162float(h0)),
                           __float2bfloat16(gn[1] - __bfloat162float(h1)));
                    *reinterpret_cast<uint32_t*>(r1 + (32 + m0p) * 2) =
                        pk(__float2bfloat16(gn[2] - __bfloat162float(h2)),
                           __float2bfloat16(gn[3] - __bfloat162float(h3)));
                }
            }
            __threadfence_block();
            BARA(1, 256);                      // gains(ch) ready
        }
    } else {
        // ================= CONSUMER warps 4-7: output GEMM =================
        const int ctid = tid - 128, cw = ctid >> 5;
        float acc[64];
        #pragma unroll
        for (int i = 0; i < 64; i++) acc[i] = 0.f;
        {   // initial prefetch B(0)
            const int grp = ms * NCHUNK;
            uint32_t nd = sb + SM_BUF;
            #pragma unroll
            for (int i = 0; i < 4; i++) {
                int o = ctid + i * 128, r = o >> 3, c = o & 7;
                CPA16(nd + BO_B + r * 144 + c * 16,
                      g_TB + (size_t)grp * 8192 + sh * 64 + r * 128 + c * 8);
            }
            CPCOMMIT();
        }
        for (int ch = 0; ch < NCHUNK; ch++) {
            const uint32_t bd = sb + SM_BUF + (ch & 1) * BUF_SZ;
            CPWAIT0();
            BARS(4, 128);                     // B(ch) landed; B(ch-1) reads done
            if (ch + 1 < NCHUNK) {
                const int grp = ms * NCHUNK + ch + 1;
                uint32_t nd = sb + SM_BUF + ((ch + 1) & 1) * BUF_SZ;
                #pragma unroll
                for (int i = 0; i < 4; i++) {
                    int o = ctid + i * 128, r = o >> 3, c = o & 7;
                    CPA16(nd + BO_B + r * 144 + c * 16,
                          g_TB + (size_t)grp * 8192 + sh * 64 + r * 128 + c * 8);
                }
                CPCOMMIT();
            }
            BARS(1, 256);                     // gains(ch) ready
            uint32_t af[2][4][4];
            #pragma unroll
            for (int rg = 0; rg < 2; rg++)
                #pragma unroll
                for (int kt = 0; kt < 4; kt++)
                    ldsm4(af[rg][kt], lmaddr(sb + SM_A2Z, cw * 32 + rg * 16, kt * 16, 144, mat, lr));
            BARA(2, 256);                     // gains(ch) consumed
            #pragma unroll
            for (int nt2 = 0; nt2 < 4; nt2++) {
                uint32_t bf[4][4];
                #pragma unroll
                for (int kt = 0; kt < 4; kt++)
                    ldsm4t(bf[kt], lmaddr(bd + BO_B, kt * 16, nt2 * 16, 144, mat, lr));
                #pragma unroll
                for (int rg = 0; rg < 2; rg++) {
                    float* a = acc + rg * 32 + nt2 * 8;
                    mmabf(a,     af[rg][0], bf[0][0], bf[0][1]);   // gh0*th0
                    mmabf(a + 4, af[rg][0], bf[0][2], bf[0][3]);
                    mmabf(a,     af[rg][2], bf[0][0], bf[0][1]);   // gl0*th0
                    mmabf(a + 4, af[rg][2], bf[0][2], bf[0][3]);
                    mmabf(a,     af[rg][1], bf[1][0], bf[1][1]);   // gh1*th1
                    mmabf(a + 4, af[rg][1], bf[1][2], bf[1][3]);
                    mmabf(a,     af[rg][3], bf[1][0], bf[1][1]);   // gl1*th1
                    mmabf(a + 4, af[rg][3], bf[1][2], bf[1][3]);
                    mmabf(a,     af[rg][0], bf[2][0], bf[2][1]);   // gh0*tl0
                    mmabf(a + 4, af[rg][0], bf[2][2], bf[2][3]);
                    mmabf(a,     af[rg][1], bf[3][0], bf[3][1]);   // gh1*tl1
                    mmabf(a + 4, af[rg][1], bf[3][2], bf[3][3]);
                }
            }
        }
        // write partials
        float* op = g_part + ((size_t)ms * NB + bb * 128 + cw * 32) * NS + sh * 64;
        #pragma unroll
        for (int rg = 0; rg < 2; rg++)
            #pragma unroll
            for (int nt2 = 0; nt2 < 4; nt2++)
                #pragma unroll
                for (int h = 0; h < 2; h++) {
                    const float* a = acc + rg * 32 + nt2 * 8 + h * 4;
                    int col = nt2 * 16 + h * 8 + 2 * t;
                    *reinterpret_cast<float2*>(op + (rg * 16 + g) * NS + col) =
                        make_float2(a[0], a[1]);
                    *reinterpret_cast<float2*>(op + (rg * 16 + g + 8) * NS + col) =
                        make_float2(a[2], a[3]);
                }
    }
}

__global__ void reduce_kernel(float* __restrict__ out) {
    int idx = blockIdx.x * blockDim.x + threadIdx.x;   // B*S/2 threads
    const float2* gp = reinterpret_cast<const float2*>(g_part);
    const size_t stride = (size_t)NB * NS / 2;
    float2 a0 = {0,0}, a1 = {0,0}, a2 = {0,0}, a3 = {0,0};
    #pragma unroll
    for (int p = 0; p < 4; p++) {
        float2 v0 = gp[(4 * p + 0) * stride + idx];
        float2 v1 = gp[(4 * p + 1) * stride + idx];
        float2 v2 = gp[(4 * p + 2) * stride + idx];
        float2 v3 = gp[(4 * p + 3) * stride + idx];
        a0.x += v0.x; a0.y += v0.y;  a1.x += v1.x; a1.y += v1.y;
        a2.x += v2.x; a2.y += v2.y;  a3.x += v3.x; a3.y += v3.y;
    }
    a0.x += a1.x + a2.x + a3.x;
    a0.y += a1.y + a2.y + a3.y;
    reinterpret_cast<float2*>(out)[idx] = a0;
}

extern "C" void kernel_launch(void* const* d_in, const int* in_sizes, int n_in,
                              void* d_out, int out_size) {
    const float* z     = (const float*)d_in[0];
    const float* zj    = (const float*)d_in[1];
    const float* vd    = (const float*)d_in[2];
    const float* that  = (const float*)d_in[3];
    const float* alpha = (const float*)d_in[4];
    const float* sp    = (const float*)d_in[5];
    const float* spr   = (const float*)d_in[6];
    float* out = (float*)d_out;

    prep_z_kernel<<<4, 256>>>(z);
    prep_m_kernel<<<NGRP, 256>>>(zj, vd, alpha, sp, spr, that);
    fused_kernel<<<dim3(NB / 128, MSPLIT, 2), 256>>>();
    reduce_kernel<<<512, 128>>>(out);
}